// round 7
// baseline (speedup 1.0000x reference)
#include <cuda_runtime.h>
#include <math_constants.h>
#include <math.h>
#include <cstdint>

#define B_   32
#define LQ   513
#define SK   1000
#define NH   8
#define DH   128
#define DM   1024
#define DLLM 4096
#define MQ   (B_*LQ)   /* 16416 */

// ---------------- scratch (no allocation allowed) ----------------
__device__ float g_tgt[(size_t)MQ * DM];     // concat(cls, target)
__device__ float g_q  [(size_t)MQ * DM];     // Q projection
__device__ float g_k  [(size_t)SK * DM];     // K projection
__device__ float g_v  [(size_t)SK * DM];     // V projection
__device__ float g_at [(size_t)MQ * DM];     // attention output
__device__ float g_wqt[(size_t)DM * DM];     // Wq^T  [1024,1024]
__device__ float g_wkt[(size_t)DM * DLLM];   // Wk^T  [1024,4096]
__device__ float g_wvt[(size_t)DM * DLLM];   // Wv^T  [1024,4096]
__device__ float g_wot[(size_t)DLLM * DM];   // Wo^T  [4096,1024]

// ================= helpers =================
__device__ __forceinline__ uint32_t smem_u32(const void* p) {
    return (uint32_t)__cvta_generic_to_shared(p);
}
__device__ __forceinline__ void cp_async16(uint32_t dst, const void* src, bool valid) {
    int sz = valid ? 16 : 0;
    asm volatile("cp.async.cg.shared.global [%0], [%1], 16, %2;\n"
                 :: "r"(dst), "l"(src), "r"(sz) : "memory");
}
__device__ __forceinline__ void cp_async_commit() {
    asm volatile("cp.async.commit_group;\n" ::: "memory");
}
__device__ __forceinline__ void cp_async_wait1() {
    asm volatile("cp.async.wait_group 1;\n" ::: "memory");
}
__device__ __forceinline__ void cp_async_wait0() {
    asm volatile("cp.async.wait_group 0;\n" ::: "memory");
}
__device__ __forceinline__ uint32_t f2tf(float x) {
    uint32_t r;
    asm("cvt.rna.tf32.f32 %0, %1;" : "=r"(r) : "f"(x));
    return r;
}
__device__ __forceinline__ void mma_tf32(float* d, const uint32_t* a, const uint32_t* b) {
    asm volatile(
        "mma.sync.aligned.m16n8k8.row.col.f32.tf32.tf32.f32 "
        "{%0,%1,%2,%3}, {%4,%5,%6,%7}, {%8,%9}, {%0,%1,%2,%3};"
        : "+f"(d[0]), "+f"(d[1]), "+f"(d[2]), "+f"(d[3])
        : "r"(a[0]), "r"(a[1]), "r"(a[2]), "r"(a[3]), "r"(b[0]), "r"(b[1]));
}

// ---------------- build tgt = [cls ; target_embedding] ----------------
__global__ void build_tgt_kernel(const float* __restrict__ tgt_emb,
                                 const float* __restrict__ cls,
                                 float* __restrict__ out)
{
    size_t i = (size_t)blockIdx.x * blockDim.x + threadIdx.x;
    size_t total = (size_t)MQ * (DM / 4);
    if (i >= total) return;
    size_t row = i / (DM / 4);
    int    c4  = (int)(i % (DM / 4));
    int b  = (int)(row / LQ);
    int lx = (int)(row % LQ);
    float4 v;
    if (lx == 0) v = ((const float4*)cls)[c4];
    else         v = ((const float4*)tgt_emb)[ ((size_t)b * (LQ-1) + (lx-1)) * (DM/4) + c4 ];
    ((float4*)out)[i] = v;
}

// ---------------- weight transpose: out[C][R] = in[R][C] ----------------
__global__ void transpose_kernel(const float* __restrict__ in,
                                 float* __restrict__ out, int R, int C)
{
    __shared__ float t[32][33];
    int bc = blockIdx.x * 32, br = blockIdx.y * 32;
    int tx = threadIdx.x, ty = threadIdx.y;          // 32 x 8
    #pragma unroll
    for (int i = 0; i < 32; i += 8)
        t[ty + i][tx] = in[(size_t)(br + ty + i) * C + bc + tx];
    __syncthreads();
    #pragma unroll
    for (int i = 0; i < 32; i += 8)
        out[(size_t)(bc + ty + i) * R + br + tx] = t[tx][ty + i];
}

// ---------------- tf32 mma.sync GEMM: C[M,N] = A[M,K] @ Bt[N,K]^T + bias ----
// CTA 128x128, BK=32, 256 thr (2x4 warps, warp tile 64x32), double-buffered cp.async.
#define PITCH 36                        /* 32 + 4 pad floats */
#define TSZ   (128 * PITCH)             /* floats per tile */
#define GEMM_SMEM (2 * 2 * TSZ * (int)sizeof(float))   /* 73728 B */

__global__ __launch_bounds__(256, 2) void tf32_gemm_kernel(
    const float* __restrict__ A, const float* __restrict__ Bt,
    const float* __restrict__ bias, float* __restrict__ C,
    int M, int N, int K)
{
    extern __shared__ float sm[];
    // layout: [stage0: A, B][stage1: A, B]
    float* As[2] = { sm,            sm + 2 * TSZ };
    float* Bs[2] = { sm + TSZ,      sm + 3 * TSZ };

    const int tid = threadIdx.x;
    const int lane = tid & 31;
    const int warp = tid >> 5;
    const int warpRow = warp >> 2;      // 0..1
    const int warpCol = warp & 3;       // 0..3
    const int groupID = lane >> 2;      // 0..7
    const int tg = lane & 3;            // 0..3

    const int rowBase = blockIdx.y * 128;
    const int colBase = blockIdx.x * 128;

    // tile-load mapping: 1024 float4 per operand per tile, 4 per thread
    const int ldRow = tid >> 1;                 // 0..127 (two threads per row)
    const int ldC4a = (tid & 1) * 4;            // base float4 in row (0 or 4)

    float acc[4][4][4];
    #pragma unroll
    for (int mt = 0; mt < 4; mt++)
        #pragma unroll
        for (int nt = 0; nt < 4; nt++)
            #pragma unroll
            for (int r = 0; r < 4; r++) acc[mt][nt][r] = 0.f;

    const int nkt = K >> 5;

    // ---- async tile loader ----
    auto load_tile = [&](int kt, int buf) {
        const int k0 = kt << 5;
        uint32_t sa = smem_u32(As[buf]);
        uint32_t sb = smem_u32(Bs[buf]);
        int gr = rowBase + ldRow;
        bool av = gr < M;
        int grc = av ? gr : 0;
        const float* ap = A  + (size_t)grc * K + k0;
        const float* bp = Bt + (size_t)(colBase + ldRow) * K + k0;
        #pragma unroll
        for (int j = 0; j < 2; j++) {
            int c4 = ldC4a + j * 2;     // float4 index 0..7 (stride 2)
            uint32_t off = (uint32_t)(ldRow * PITCH + c4 * 4) * 4;
            cp_async16(sa + off, ap + c4 * 4, av);
            cp_async16(sb + off, bp + c4 * 4, true);
        }
        // second pair
        #pragma unroll
        for (int j = 0; j < 2; j++) {
            int c4 = ldC4a + j * 2 + 1;
            uint32_t off = (uint32_t)(ldRow * PITCH + c4 * 4) * 4;
            cp_async16(sa + off, ap + c4 * 4, av);
            cp_async16(sb + off, bp + c4 * 4, true);
        }
    };

    load_tile(0, 0);
    cp_async_commit();

    int buf = 0;
    for (int kt = 0; kt < nkt; kt++) {
        if (kt + 1 < nkt) {
            load_tile(kt + 1, buf ^ 1);
            cp_async_commit();
            cp_async_wait1();
        } else {
            cp_async_wait0();
        }
        __syncthreads();

        const float* At = As[buf];
        const float* Btile = Bs[buf];
        #pragma unroll
        for (int kk = 0; kk < 32; kk += 8) {
            uint32_t afrag[4][4];
            #pragma unroll
            for (int mt = 0; mt < 4; mt++) {
                int m0 = warpRow * 64 + mt * 16;
                const float* p0 = At + (m0 + groupID) * PITCH + kk + tg;
                const float* p1 = At + (m0 + 8 + groupID) * PITCH + kk + tg;
                afrag[mt][0] = f2tf(p0[0]);
                afrag[mt][1] = f2tf(p1[0]);
                afrag[mt][2] = f2tf(p0[4]);
                afrag[mt][3] = f2tf(p1[4]);
            }
            uint32_t bfrag[4][2];
            #pragma unroll
            for (int nt = 0; nt < 4; nt++) {
                int n0 = warpCol * 32 + nt * 8;
                const float* p = Btile + (n0 + groupID) * PITCH + kk + tg;
                bfrag[nt][0] = f2tf(p[0]);
                bfrag[nt][1] = f2tf(p[4]);
            }
            #pragma unroll
            for (int mt = 0; mt < 4; mt++)
                #pragma unroll
                for (int nt = 0; nt < 4; nt++)
                    mma_tf32(acc[mt][nt], afrag[mt], bfrag[nt]);
        }
        __syncthreads();
        buf ^= 1;
    }

    // ---- epilogue: +bias, float2 stores (full 32B sectors) ----
    #pragma unroll
    for (int nt = 0; nt < 4; nt++) {
        int gn = colBase + warpCol * 32 + nt * 8 + 2 * tg;
        float bx = bias[gn], by = bias[gn + 1];
        #pragma unroll
        for (int mt = 0; mt < 4; mt++) {
            int gm0 = rowBase + warpRow * 64 + mt * 16 + groupID;
            if (gm0 < M) {
                float2 v = make_float2(acc[mt][nt][0] + bx, acc[mt][nt][1] + by);
                *(float2*)&C[(size_t)gm0 * N + gn] = v;
            }
            if (gm0 + 8 < M) {
                float2 v = make_float2(acc[mt][nt][2] + bx, acc[mt][nt][3] + by);
                *(float2*)&C[(size_t)(gm0 + 8) * N + gn] = v;
            }
        }
    }
}

// ---------------- fused attention (flash-style, fp32) ----------------
#define BQ 64
#define BS 32
#define QPITCH (DH + 4)
#define SPITCH (BS + 1)
#define SMEM_ATTN ((BQ*QPITCH + 2*BS*QPITCH + BQ*SPITCH) * (int)sizeof(float))

__global__ __launch_bounds__(256) void attn_kernel()
{
    extern __shared__ float sm[];
    float* Qs = sm;
    float* Ks = Qs + BQ * QPITCH;
    float* Vs = Ks + BS * QPITCH;
    float* Ss = Vs + BS * QPITCH;

    const int tid = threadIdx.x;
    const int qt = blockIdx.x, h = blockIdx.y, b = blockIdx.z;
    const int q0 = qt * BQ;
    const int row = tid >> 2;
    const int cg  = tid & 3;
    const float SCALE = 0.08838834764831845f;

    for (int i = tid; i < BQ * (DH / 4); i += 256) {
        int r = i / (DH / 4);
        int c4 = (i % (DH / 4)) * 4;
        float4 v = make_float4(0.f, 0.f, 0.f, 0.f);
        int gq = q0 + r;
        if (gq < LQ)
            v = *(const float4*)&g_q[((size_t)b * LQ + gq) * DM + h * DH + c4];
        *(float4*)&Qs[r * QPITCH + c4] = v;
    }

    float acc[32];
    #pragma unroll
    for (int c = 0; c < 32; c++) acc[c] = 0.f;
    float m = -CUDART_INF_F, l = 0.f;

    for (int s0 = 0; s0 < SK; s0 += BS) {
        __syncthreads();
        for (int i = tid; i < BS * (DH / 4); i += 256) {
            int r = i / (DH / 4);
            int c4 = (i % (DH / 4)) * 4;
            int gs = s0 + r;
            float4 kv = make_float4(0.f, 0.f, 0.f, 0.f);
            float4 vv = kv;
            if (gs < SK) {
                kv = *(const float4*)&g_k[(size_t)gs * DM + h * DH + c4];
                vv = *(const float4*)&g_v[(size_t)gs * DM + h * DH + c4];
            }
            *(float4*)&Ks[r * QPITCH + c4] = kv;
            *(float4*)&Vs[r * QPITCH + c4] = vv;
        }
        __syncthreads();

        float dot[8];
        #pragma unroll
        for (int j = 0; j < 8; j++) dot[j] = 0.f;
        #pragma unroll 8
        for (int e = 0; e < DH; e += 4) {
            float4 qv = *(float4*)&Qs[row * QPITCH + e];
            #pragma unroll
            for (int j = 0; j < 8; j++) {
                float4 kv = *(float4*)&Ks[(4 * j + cg) * QPITCH + e];
                dot[j] += qv.x * kv.x + qv.y * kv.y + qv.z * kv.z + qv.w * kv.w;
            }
        }
        #pragma unroll
        for (int j = 0; j < 8; j++) {
            int col = 4 * j + cg;
            Ss[row * SPITCH + col] = (s0 + col < SK) ? dot[j] * SCALE : -CUDART_INF_F;
        }
        __syncthreads();

        float tm = -CUDART_INF_F;
        #pragma unroll
        for (int c = 0; c < BS; c++) tm = fmaxf(tm, Ss[row * SPITCH + c]);
        float mnew  = fmaxf(m, tm);
        float alpha = __expf(m - mnew);
        l *= alpha;
        #pragma unroll
        for (int c = 0; c < 32; c++) acc[c] *= alpha;
        for (int k = 0; k < BS; k++) {
            float pk = __expf(Ss[row * SPITCH + k] - mnew);
            l += pk;
            const float* vrow = &Vs[k * QPITCH];
            #pragma unroll
            for (int c = 0; c < 32; c++)
                acc[c] += pk * vrow[4 * c + cg];
        }
        m = mnew;
    }

    int gq = q0 + row;
    if (gq < LQ) {
        float inv = 1.0f / l;
        size_t base = ((size_t)b * LQ + gq) * DM + h * DH;
        #pragma unroll
        for (int c = 0; c < 32; c++)
            g_at[base + 4 * c + cg] = acc[c] * inv;
    }
}

// ---------------- launcher ----------------
extern "C" void kernel_launch(void* const* d_in, const int* in_sizes, int n_in,
                              void* d_out, int out_size)
{
    const float* tgt = (const float*)d_in[0];
    const float* src = (const float*)d_in[1];
    const float* val = (const float*)d_in[2];
    const float* Wq  = (const float*)d_in[3];
    const float* bq  = (const float*)d_in[4];
    const float* Wk  = (const float*)d_in[5];
    const float* bk  = (const float*)d_in[6];
    const float* Wv  = (const float*)d_in[7];
    const float* bv  = (const float*)d_in[8];
    const float* Wo  = (const float*)d_in[9];
    const float* bo  = (const float*)d_in[10];
    const float* cls = (const float*)d_in[11];

    float *p_tgt, *p_q, *p_k, *p_v, *p_at, *p_wqt, *p_wkt, *p_wvt, *p_wot;
    cudaGetSymbolAddress((void**)&p_tgt, g_tgt);
    cudaGetSymbolAddress((void**)&p_q,   g_q);
    cudaGetSymbolAddress((void**)&p_k,   g_k);
    cudaGetSymbolAddress((void**)&p_v,   g_v);
    cudaGetSymbolAddress((void**)&p_at,  g_at);
    cudaGetSymbolAddress((void**)&p_wqt, g_wqt);
    cudaGetSymbolAddress((void**)&p_wkt, g_wkt);
    cudaGetSymbolAddress((void**)&p_wvt, g_wvt);
    cudaGetSymbolAddress((void**)&p_wot, g_wot);

    cudaFuncSetAttribute(tf32_gemm_kernel, cudaFuncAttributeMaxDynamicSharedMemorySize, GEMM_SMEM);
    cudaFuncSetAttribute(attn_kernel,      cudaFuncAttributeMaxDynamicSharedMemorySize, SMEM_ATTN);

    dim3 tb(32, 8);
    transpose_kernel<<<dim3(DM / 32,   DM / 32),   tb>>>(Wq, p_wqt, DM,   DM);
    transpose_kernel<<<dim3(DM / 32,   DLLM / 32), tb>>>(Wk, p_wkt, DLLM, DM);
    transpose_kernel<<<dim3(DM / 32,   DLLM / 32), tb>>>(Wv, p_wvt, DLLM, DM);
    transpose_kernel<<<dim3(DLLM / 32, DM / 32),   tb>>>(Wo, p_wot, DM,   DLLM);

    {
        size_t total = (size_t)MQ * (DM / 4);
        build_tgt_kernel<<<(int)((total + 255) / 256), 256>>>(tgt, cls, p_tgt);
    }

    // Q = tgt @ Wq + bq            [16416,1024]
    tf32_gemm_kernel<<<dim3(DM / 128, (MQ + 127) / 128), 256, GEMM_SMEM>>>(p_tgt, p_wqt, bq, p_q, MQ, DM, DM);
    // K = src @ Wk + bk            [1000,1024]
    tf32_gemm_kernel<<<dim3(DM / 128, (SK + 127) / 128), 256, GEMM_SMEM>>>(src, p_wkt, bk, p_k, SK, DM, DLLM);
    // V = val @ Wv + bv
    tf32_gemm_kernel<<<dim3(DM / 128, (SK + 127) / 128), 256, GEMM_SMEM>>>(val, p_wvt, bv, p_v, SK, DM, DLLM);
    // attention
    attn_kernel<<<dim3((LQ + BQ - 1) / BQ, NH, B_), 256, SMEM_ATTN>>>();
    // out = attn @ Wo + bo         [16416,4096]
    tf32_gemm_kernel<<<dim3(DLLM / 128, (MQ + 127) / 128), 256, GEMM_SMEM>>>(p_at, p_wot, bo, (float*)d_out, MQ, DLLM, DM);
}

// round 10
// speedup vs baseline: 2.0479x; 2.0479x over previous
#include <cuda_runtime.h>
#include <cuda_fp16.h>
#include <math_constants.h>
#include <math.h>
#include <cstdint>

#define B_   32
#define LQ   513
#define SK   1000
#define NH   8
#define DH   128
#define DM   1024
#define DLLM 4096
#define MQ   (B_*LQ)   /* 16416 */

// ---------------- scratch (no allocation allowed) ----------------
__device__ float  g_q  [(size_t)MQ * DM];
__device__ float  g_k  [(size_t)SK * DM];
__device__ float  g_v  [(size_t)SK * DM];
__device__ __half h_tgt[(size_t)MQ * DM];
__device__ __half h_src[(size_t)SK * DLLM];
__device__ __half h_val[(size_t)SK * DLLM];
__device__ __half h_at [(size_t)MQ * DM];
__device__ __half h_wqt[(size_t)DM * DM];
__device__ __half h_wkt[(size_t)DM * DLLM];
__device__ __half h_wvt[(size_t)DM * DLLM];
__device__ __half h_wot[(size_t)DLLM * DM];

// ================= helpers =================
__device__ __forceinline__ uint32_t smem_u32(const void* p) {
    return (uint32_t)__cvta_generic_to_shared(p);
}
__device__ __forceinline__ void cp_async16(uint32_t dst, const void* src, bool valid) {
    int sz = valid ? 16 : 0;
    asm volatile("cp.async.cg.shared.global [%0], [%1], 16, %2;\n"
                 :: "r"(dst), "l"(src), "r"(sz) : "memory");
}
__device__ __forceinline__ void cp_async_commit() {
    asm volatile("cp.async.commit_group;\n" ::: "memory");
}
__device__ __forceinline__ void cp_async_wait1() {
    asm volatile("cp.async.wait_group 1;\n" ::: "memory");
}
__device__ __forceinline__ void cp_async_wait0() {
    asm volatile("cp.async.wait_group 0;\n" ::: "memory");
}
__device__ __forceinline__ void ldsm4(uint32_t& r0, uint32_t& r1, uint32_t& r2, uint32_t& r3,
                                      uint32_t addr) {
    asm volatile("ldmatrix.sync.aligned.m8n8.x4.shared.b16 {%0,%1,%2,%3}, [%4];"
                 : "=r"(r0), "=r"(r1), "=r"(r2), "=r"(r3) : "r"(addr));
}
__device__ __forceinline__ void mma_f16(float* d, const uint32_t* a, const uint32_t* b) {
    asm volatile(
        "mma.sync.aligned.m16n8k16.row.col.f32.f16.f16.f32 "
        "{%0,%1,%2,%3}, {%4,%5,%6,%7}, {%8,%9}, {%0,%1,%2,%3};"
        : "+f"(d[0]), "+f"(d[1]), "+f"(d[2]), "+f"(d[3])
        : "r"(a[0]), "r"(a[1]), "r"(a[2]), "r"(a[3]), "r"(b[0]), "r"(b[1]));
}

// ---------------- build tgt = [cls ; target_embedding] -> half ----------------
__global__ void build_tgt_h_kernel(const float* __restrict__ tgt_emb,
                                   const float* __restrict__ cls,
                                   __half* __restrict__ out)
{
    size_t i = (size_t)blockIdx.x * blockDim.x + threadIdx.x;
    size_t total = (size_t)MQ * (DM / 4);
    if (i >= total) return;
    size_t row = i / (DM / 4);
    int    c4  = (int)(i % (DM / 4));
    int b  = (int)(row / LQ);
    int lx = (int)(row % LQ);
    float4 v;
    if (lx == 0) v = ((const float4*)cls)[c4];
    else         v = ((const float4*)tgt_emb)[ ((size_t)b * (LQ-1) + (lx-1)) * (DM/4) + c4 ];
    __half2 h0 = __floats2half2_rn(v.x, v.y);
    __half2 h1 = __floats2half2_rn(v.z, v.w);
    uint2 u = make_uint2(*(uint32_t*)&h0, *(uint32_t*)&h1);
    *(uint2*)&out[i * 4] = u;
}

// ---------------- float -> half copy ----------------
__global__ void f2h_kernel(const float* __restrict__ in, __half* __restrict__ out, size_t n4)
{
    size_t i = (size_t)blockIdx.x * blockDim.x + threadIdx.x;
    if (i >= n4) return;
    float4 v = ((const float4*)in)[i];
    __half2 h0 = __floats2half2_rn(v.x, v.y);
    __half2 h1 = __floats2half2_rn(v.z, v.w);
    uint2 u = make_uint2(*(uint32_t*)&h0, *(uint32_t*)&h1);
    *(uint2*)&out[i * 4] = u;
}

// ---------------- weight transpose -> half: out[C][R] = half(in[R][C]) ------
__global__ void transpose_h_kernel(const float* __restrict__ in,
                                   __half* __restrict__ out, int R, int C)
{
    __shared__ float t[32][33];
    int bc = blockIdx.x * 32, br = blockIdx.y * 32;
    int tx = threadIdx.x, ty = threadIdx.y;          // 32 x 8
    #pragma unroll
    for (int i = 0; i < 32; i += 8)
        t[ty + i][tx] = in[(size_t)(br + ty + i) * C + bc + tx];
    __syncthreads();
    #pragma unroll
    for (int i = 0; i < 32; i += 8)
        out[(size_t)(bc + ty + i) * R + br + tx] = __float2half_rn(t[tx][ty + i]);
}

// ---------------- fp16 mma GEMM: C[M,N] = A[M,K] @ Bt[N,K]^T + bias ---------
// CTA 128x128, BK=64, 256 thr (2x4 warps, warp tile 64x32), double-buffered
// cp.async, XOR-swizzled 128B smem rows, ldmatrix fragment loads.
#define HTILEB 16384                     /* 128 rows x 128B  per operand */
#define HGEMM_SMEM (4 * HTILEB)          /* 65536 */

__global__ __launch_bounds__(256, 2) void hgemm_kernel(
    const __half* __restrict__ A, const __half* __restrict__ Bt,
    const float* __restrict__ bias, float* __restrict__ C,
    int M, int N, int K)
{
    extern __shared__ char smemc[];
    const uint32_t s0 = smem_u32(smemc);
    const uint32_t SA[2] = { s0,          s0 + 2 * HTILEB };
    const uint32_t SB[2] = { s0 + HTILEB, s0 + 3 * HTILEB };

    const int tid = threadIdx.x;
    const int lane = tid & 31, warp = tid >> 5;
    const int warpRow = warp >> 2;       // 0..1
    const int warpCol = warp & 3;        // 0..3
    const int groupID = lane >> 2, tg = lane & 3;
    const int rowBase = blockIdx.y * 128;
    const int colBase = blockIdx.x * 128;

    // tile loader mapping: 2048 chunks(16B)/tile-pair, 8 per thread
    const int ldRow = tid >> 1;          // 0..127
    const int ldCb  = (tid & 1) * 4;     // chunk base 0 or 4

    // fragment lane components
    const int aR = lane & 15;
    const uint32_t aK = (uint32_t)((lane >> 4) & 1) * 16;
    const int bR = (lane & 7) + ((lane >> 4) << 3);
    const uint32_t bK = (uint32_t)((lane >> 3) & 1) * 16;

    float acc[4][4][4];
    #pragma unroll
    for (int mt = 0; mt < 4; mt++)
        #pragma unroll
        for (int nt = 0; nt < 4; nt++)
            #pragma unroll
            for (int r = 0; r < 4; r++) acc[mt][nt][r] = 0.f;

    const int nkt = K >> 6;

    auto load_tile = [&](int kt, int buf) {
        const int k0 = kt << 6;
        int gr = rowBase + ldRow;
        bool av = gr < M;
        const __half* ap = A  + (size_t)(av ? gr : 0) * K + k0;
        const __half* bp = Bt + (size_t)(colBase + ldRow) * K + k0;
        const uint32_t rsw = (uint32_t)((ldRow & 7) << 4);
        const uint32_t rowoff = (uint32_t)(ldRow << 7);
        #pragma unroll
        for (int j = 0; j < 4; j++) {
            int c = ldCb + j;
            uint32_t off = (rowoff + (uint32_t)(c << 4)) ^ rsw;
            cp_async16(SA[buf] + off, ap + c * 8, av);
            cp_async16(SB[buf] + off, bp + c * 8, true);
        }
    };

    load_tile(0, 0);
    cp_async_commit();

    int buf = 0;
    for (int kt = 0; kt < nkt; kt++) {
        if (kt + 1 < nkt) {
            load_tile(kt + 1, buf ^ 1);
            cp_async_commit();
            cp_async_wait1();
        } else {
            cp_async_wait0();
        }
        __syncthreads();

        const uint32_t sa = SA[buf], sb = SB[buf];
        #pragma unroll
        for (int kk = 0; kk < 4; kk++) {
            uint32_t af[4][4];
            #pragma unroll
            for (int mt = 0; mt < 4; mt++) {
                int r = warpRow * 64 + mt * 16 + aR;
                uint32_t byte = ((uint32_t)(r << 7) + (uint32_t)(kk << 5) + aK)
                                ^ (uint32_t)((r & 7) << 4);
                ldsm4(af[mt][0], af[mt][1], af[mt][2], af[mt][3], sa + byte);
            }
            uint32_t bf[2][4];
            #pragma unroll
            for (int ng = 0; ng < 2; ng++) {
                int r = warpCol * 32 + ng * 16 + bR;
                uint32_t byte = ((uint32_t)(r << 7) + (uint32_t)(kk << 5) + bK)
                                ^ (uint32_t)((r & 7) << 4);
                ldsm4(bf[ng][0], bf[ng][1], bf[ng][2], bf[ng][3], sb + byte);
            }
            #pragma unroll
            for (int mt = 0; mt < 4; mt++) {
                mma_f16(acc[mt][0], af[mt], &bf[0][0]);
                mma_f16(acc[mt][1], af[mt], &bf[0][2]);
                mma_f16(acc[mt][2], af[mt], &bf[1][0]);
                mma_f16(acc[mt][3], af[mt], &bf[1][2]);
            }
        }
        __syncthreads();
        buf ^= 1;
    }

    // ---- epilogue: +bias, float2 stores ----
    #pragma unroll
    for (int nt = 0; nt < 4; nt++) {
        int gn = colBase + warpCol * 32 + nt * 8 + 2 * tg;
        float bx = bias[gn], by = bias[gn + 1];
        #pragma unroll
        for (int mt = 0; mt < 4; mt++) {
            int gm0 = rowBase + warpRow * 64 + mt * 16 + groupID;
            if (gm0 < M) {
                float2 v = make_float2(acc[mt][nt][0] + bx, acc[mt][nt][1] + by);
                *(float2*)&C[(size_t)gm0 * N + gn] = v;
            }
            if (gm0 + 8 < M) {
                float2 v = make_float2(acc[mt][nt][2] + bx, acc[mt][nt][3] + by);
                *(float2*)&C[(size_t)(gm0 + 8) * N + gn] = v;
            }
        }
    }
}

// ---------------- fused attention (flash-style, fp32; writes half) ----------
#define BQ 64
#define BS 32
#define QPITCH (DH + 4)
#define SPITCH (BS + 1)
#define SMEM_ATTN ((BQ*QPITCH + 2*BS*QPITCH + BQ*SPITCH) * (int)sizeof(float))

__global__ __launch_bounds__(256) void attn_kernel()
{
    extern __shared__ float sm[];
    float* Qs = sm;
    float* Ks = Qs + BQ * QPITCH;
    float* Vs = Ks + BS * QPITCH;
    float* Ss = Vs + BS * QPITCH;

    const int tid = threadIdx.x;
    const int qt = blockIdx.x, h = blockIdx.y, b = blockIdx.z;
    const int q0 = qt * BQ;
    const int row = tid >> 2;
    const int cg  = tid & 3;
    const float SCALE = 0.08838834764831845f;

    for (int i = tid; i < BQ * (DH / 4); i += 256) {
        int r = i / (DH / 4);
        int c4 = (i % (DH / 4)) * 4;
        float4 v = make_float4(0.f, 0.f, 0.f, 0.f);
        int gq = q0 + r;
        if (gq < LQ)
            v = *(const float4*)&g_q[((size_t)b * LQ + gq) * DM + h * DH + c4];
        *(float4*)&Qs[r * QPITCH + c4] = v;
    }

    float acc[32];
    #pragma unroll
    for (int c = 0; c < 32; c++) acc[c] = 0.f;
    float m = -CUDART_INF_F, l = 0.f;

    for (int s0 = 0; s0 < SK; s0 += BS) {
        __syncthreads();
        for (int i = tid; i < BS * (DH / 4); i += 256) {
            int r = i / (DH / 4);
            int c4 = (i % (DH / 4)) * 4;
            int gs = s0 + r;
            float4 kv = make_float4(0.f, 0.f, 0.f, 0.f);
            float4 vv = kv;
            if (gs < SK) {
                kv = *(const float4*)&g_k[(size_t)gs * DM + h * DH + c4];
                vv = *(const float4*)&g_v[(size_t)gs * DM + h * DH + c4];
            }
            *(float4*)&Ks[r * QPITCH + c4] = kv;
            *(float4*)&Vs[r * QPITCH + c4] = vv;
        }
        __syncthreads();

        float dot[8];
        #pragma unroll
        for (int j = 0; j < 8; j++) dot[j] = 0.f;
        #pragma unroll 8
        for (int e = 0; e < DH; e += 4) {
            float4 qv = *(float4*)&Qs[row * QPITCH + e];
            #pragma unroll
            for (int j = 0; j < 8; j++) {
                float4 kv = *(float4*)&Ks[(4 * j + cg) * QPITCH + e];
                dot[j] += qv.x * kv.x + qv.y * kv.y + qv.z * kv.z + qv.w * kv.w;
            }
        }
        #pragma unroll
        for (int j = 0; j < 8; j++) {
            int col = 4 * j + cg;
            Ss[row * SPITCH + col] = (s0 + col < SK) ? dot[j] * SCALE : -CUDART_INF_F;
        }
        __syncthreads();

        float tm = -CUDART_INF_F;
        #pragma unroll
        for (int c = 0; c < BS; c++) tm = fmaxf(tm, Ss[row * SPITCH + c]);
        float mnew  = fmaxf(m, tm);
        float alpha = __expf(m - mnew);
        l *= alpha;
        #pragma unroll
        for (int c = 0; c < 32; c++) acc[c] *= alpha;
        for (int k = 0; k < BS; k++) {
            float pk = __expf(Ss[row * SPITCH + k] - mnew);
            l += pk;
            const float* vrow = &Vs[k * QPITCH];
            #pragma unroll
            for (int c = 0; c < 32; c++)
                acc[c] += pk * vrow[4 * c + cg];
        }
        m = mnew;
    }

    int gq = q0 + row;
    if (gq < LQ) {
        float inv = 1.0f / l;
        size_t base = ((size_t)b * LQ + gq) * DM + h * DH;
        #pragma unroll
        for (int c = 0; c < 32; c++)
            h_at[base + 4 * c + cg] = __float2half_rn(acc[c] * inv);
    }
}

// ---------------- launcher ----------------
extern "C" void kernel_launch(void* const* d_in, const int* in_sizes, int n_in,
                              void* d_out, int out_size)
{
    const float* tgt = (const float*)d_in[0];
    const float* src = (const float*)d_in[1];
    const float* val = (const float*)d_in[2];
    const float* Wq  = (const float*)d_in[3];
    const float* bq  = (const float*)d_in[4];
    const float* Wk  = (const float*)d_in[5];
    const float* bk  = (const float*)d_in[6];
    const float* Wv  = (const float*)d_in[7];
    const float* bv  = (const float*)d_in[8];
    const float* Wo  = (const float*)d_in[9];
    const float* bo  = (const float*)d_in[10];
    const float* cls = (const float*)d_in[11];

    float  *p_q, *p_k, *p_v;
    __half *p_tgt, *p_src, *p_val, *p_at, *p_wqt, *p_wkt, *p_wvt, *p_wot;
    cudaGetSymbolAddress((void**)&p_q,   g_q);
    cudaGetSymbolAddress((void**)&p_k,   g_k);
    cudaGetSymbolAddress((void**)&p_v,   g_v);
    cudaGetSymbolAddress((void**)&p_tgt, h_tgt);
    cudaGetSymbolAddress((void**)&p_src, h_src);
    cudaGetSymbolAddress((void**)&p_val, h_val);
    cudaGetSymbolAddress((void**)&p_at,  h_at);
    cudaGetSymbolAddress((void**)&p_wqt, h_wqt);
    cudaGetSymbolAddress((void**)&p_wkt, h_wkt);
    cudaGetSymbolAddress((void**)&p_wvt, h_wvt);
    cudaGetSymbolAddress((void**)&p_wot, h_wot);

    cudaFuncSetAttribute(hgemm_kernel, cudaFuncAttributeMaxDynamicSharedMemorySize, HGEMM_SMEM);
    cudaFuncSetAttribute(attn_kernel,  cudaFuncAttributeMaxDynamicSharedMemorySize, SMEM_ATTN);

    dim3 tb(32, 8);
    // weight transpose + convert to half
    transpose_h_kernel<<<dim3(DM / 32,   DM / 32),   tb>>>(Wq, p_wqt, DM,   DM);
    transpose_h_kernel<<<dim3(DM / 32,   DLLM / 32), tb>>>(Wk, p_wkt, DLLM, DM);
    transpose_h_kernel<<<dim3(DM / 32,   DLLM / 32), tb>>>(Wv, p_wvt, DLLM, DM);
    transpose_h_kernel<<<dim3(DLLM / 32, DM / 32),   tb>>>(Wo, p_wot, DM,   DLLM);

    // activations -> half
    {
        size_t total = (size_t)MQ * (DM / 4);
        build_tgt_h_kernel<<<(int)((total + 255) / 256), 256>>>(tgt, cls, p_tgt);
        size_t n4 = (size_t)SK * DLLM / 4;
        f2h_kernel<<<(int)((n4 + 255) / 256), 256>>>(src, p_src, n4);
        f2h_kernel<<<(int)((n4 + 255) / 256), 256>>>(val, p_val, n4);
    }

    // Q = tgt @ Wq + bq            [16416,1024]
    hgemm_kernel<<<dim3(DM / 128, (MQ + 127) / 128), 256, HGEMM_SMEM>>>(p_tgt, p_wqt, bq, p_q, MQ, DM, DM);
    // K = src @ Wk + bk            [1000,1024]
    hgemm_kernel<<<dim3(DM / 128, (SK + 127) / 128), 256, HGEMM_SMEM>>>(p_src, p_wkt, bk, p_k, SK, DM, DLLM);
    // V = val @ Wv + bv
    hgemm_kernel<<<dim3(DM / 128, (SK + 127) / 128), 256, HGEMM_SMEM>>>(p_val, p_wvt, bv, p_v, SK, DM, DLLM);
    // attention (fp32 in, half out)
    attn_kernel<<<dim3((LQ + BQ - 1) / BQ, NH, B_), 256, SMEM_ATTN>>>();
    // out = attn @ Wo + bo         [16416,4096]
    hgemm_kernel<<<dim3(DLLM / 128, (MQ + 127) / 128), 256, HGEMM_SMEM>>>(p_at, p_wot, bo, (float*)d_out, MQ, DLLM, DM);
}

// round 13
// speedup vs baseline: 8.5488x; 4.1744x over previous
#include <cuda_runtime.h>
#include <cuda_fp16.h>
#include <math_constants.h>
#include <math.h>
#include <cstdint>

#define B_   32
#define LQ   513
#define SK   1000
#define NH   8
#define DH   128
#define DM   1024
#define DLLM 4096
#define MQ   (B_*LQ)   /* 16416 */

// ---------------- scratch (no allocation allowed) ----------------
__device__ __half h_tgt[(size_t)MQ * DM];
__device__ __half h_src[(size_t)SK * DLLM];
__device__ __half h_val[(size_t)SK * DLLM];
__device__ __half h_q  [(size_t)MQ * DM];
__device__ __half h_k  [(size_t)SK * DM];
__device__ __half h_v  [(size_t)SK * DM];
__device__ __half h_at [(size_t)MQ * DM];
__device__ __half h_wqt[(size_t)DM * DM];
__device__ __half h_wkt[(size_t)DM * DLLM];
__device__ __half h_wvt[(size_t)DM * DLLM];
__device__ __half h_wot[(size_t)DLLM * DM];

// ================= helpers =================
__device__ __forceinline__ uint32_t smem_u32(const void* p) {
    return (uint32_t)__cvta_generic_to_shared(p);
}
__device__ __forceinline__ void cp_async16(uint32_t dst, const void* src, bool valid) {
    int sz = valid ? 16 : 0;
    asm volatile("cp.async.cg.shared.global [%0], [%1], 16, %2;\n"
                 :: "r"(dst), "l"(src), "r"(sz) : "memory");
}
__device__ __forceinline__ void cp_async_commit() {
    asm volatile("cp.async.commit_group;\n" ::: "memory");
}
__device__ __forceinline__ void cp_async_wait1() {
    asm volatile("cp.async.wait_group 1;\n" ::: "memory");
}
__device__ __forceinline__ void cp_async_wait0() {
    asm volatile("cp.async.wait_group 0;\n" ::: "memory");
}
__device__ __forceinline__ void ldsm4(uint32_t& r0, uint32_t& r1, uint32_t& r2, uint32_t& r3,
                                      uint32_t addr) {
    asm volatile("ldmatrix.sync.aligned.m8n8.x4.shared.b16 {%0,%1,%2,%3}, [%4];"
                 : "=r"(r0), "=r"(r1), "=r"(r2), "=r"(r3) : "r"(addr));
}
__device__ __forceinline__ void ldsm4t(uint32_t& r0, uint32_t& r1, uint32_t& r2, uint32_t& r3,
                                       uint32_t addr) {
    asm volatile("ldmatrix.sync.aligned.m8n8.x4.trans.shared.b16 {%0,%1,%2,%3}, [%4];"
                 : "=r"(r0), "=r"(r1), "=r"(r2), "=r"(r3) : "r"(addr));
}
__device__ __forceinline__ void mma_f16(float* d, const uint32_t* a, const uint32_t* b) {
    asm volatile(
        "mma.sync.aligned.m16n8k16.row.col.f32.f16.f16.f32 "
        "{%0,%1,%2,%3}, {%4,%5,%6,%7}, {%8,%9}, {%0,%1,%2,%3};"
        : "+f"(d[0]), "+f"(d[1]), "+f"(d[2]), "+f"(d[3])
        : "r"(a[0]), "r"(a[1]), "r"(a[2]), "r"(a[3]), "r"(b[0]), "r"(b[1]));
}
__device__ __forceinline__ uint32_t h2bits(float a, float b) {
    __half2 h = __floats2half2_rn(a, b);
    return *(uint32_t*)&h;
}

// ---------------- build tgt = [cls ; target_embedding] -> half ----------------
__global__ void build_tgt_h_kernel(const float* __restrict__ tgt_emb,
                                   const float* __restrict__ cls,
                                   __half* __restrict__ out)
{
    size_t i = (size_t)blockIdx.x * blockDim.x + threadIdx.x;
    size_t total = (size_t)MQ * (DM / 4);
    if (i >= total) return;
    size_t row = i / (DM / 4);
    int    c4  = (int)(i % (DM / 4));
    int b  = (int)(row / LQ);
    int lx = (int)(row % LQ);
    float4 v;
    if (lx == 0) v = ((const float4*)cls)[c4];
    else         v = ((const float4*)tgt_emb)[ ((size_t)b * (LQ-1) + (lx-1)) * (DM/4) + c4 ];
    __half2 h0 = __floats2half2_rn(v.x, v.y);
    __half2 h1 = __floats2half2_rn(v.z, v.w);
    uint2 u = make_uint2(*(uint32_t*)&h0, *(uint32_t*)&h1);
    *(uint2*)&out[i * 4] = u;
}

// ---------------- float -> half copy ----------------
__global__ void f2h_kernel(const float* __restrict__ in, __half* __restrict__ out, size_t n4)
{
    size_t i = (size_t)blockIdx.x * blockDim.x + threadIdx.x;
    if (i >= n4) return;
    float4 v = ((const float4*)in)[i];
    __half2 h0 = __floats2half2_rn(v.x, v.y);
    __half2 h1 = __floats2half2_rn(v.z, v.w);
    uint2 u = make_uint2(*(uint32_t*)&h0, *(uint32_t*)&h1);
    *(uint2*)&out[i * 4] = u;
}

// ---------------- weight transpose -> half ----------------
__global__ void transpose_h_kernel(const float* __restrict__ in,
                                   __half* __restrict__ out, int R, int C)
{
    __shared__ float t[32][33];
    int bc = blockIdx.x * 32, br = blockIdx.y * 32;
    int tx = threadIdx.x, ty = threadIdx.y;          // 32 x 8
    #pragma unroll
    for (int i = 0; i < 32; i += 8)
        t[ty + i][tx] = in[(size_t)(br + ty + i) * C + bc + tx];
    __syncthreads();
    #pragma unroll
    for (int i = 0; i < 32; i += 8)
        out[(size_t)(bc + ty + i) * R + br + tx] = __float2half_rn(t[tx][ty + i]);
}

// ---------------- fp16 mma GEMM: C[M,N] = A[M,K] @ Bt[N,K]^T + bias ---------
#define HTILEB 16384
#define HGEMM_SMEM (4 * HTILEB)

template <bool HOUT>
__global__ __launch_bounds__(256, 2) void hgemm_kernel(
    const __half* __restrict__ A, const __half* __restrict__ Bt,
    const float* __restrict__ bias, void* __restrict__ Cv,
    int M, int N, int K)
{
    extern __shared__ char smemc[];
    const uint32_t s0 = smem_u32(smemc);
    const uint32_t SA[2] = { s0,          s0 + 2 * HTILEB };
    const uint32_t SB[2] = { s0 + HTILEB, s0 + 3 * HTILEB };

    const int tid = threadIdx.x;
    const int lane = tid & 31, warp = tid >> 5;
    const int warpRow = warp >> 2;
    const int warpCol = warp & 3;
    const int groupID = lane >> 2, tg = lane & 3;
    const int rowBase = blockIdx.y * 128;
    const int colBase = blockIdx.x * 128;

    const int ldRow = tid >> 1;
    const int ldCb  = (tid & 1) * 4;

    const int aR = lane & 15;
    const uint32_t aK = (uint32_t)((lane >> 4) & 1) * 16;
    const int bR = (lane & 7) + ((lane >> 4) << 3);
    const uint32_t bK = (uint32_t)((lane >> 3) & 1) * 16;

    float acc[4][4][4];
    #pragma unroll
    for (int mt = 0; mt < 4; mt++)
        #pragma unroll
        for (int nt = 0; nt < 4; nt++)
            #pragma unroll
            for (int r = 0; r < 4; r++) acc[mt][nt][r] = 0.f;

    const int nkt = K >> 6;

    auto load_tile = [&](int kt, int buf) {
        const int k0 = kt << 6;
        int gr = rowBase + ldRow;
        bool av = gr < M;
        const __half* ap = A  + (size_t)(av ? gr : 0) * K + k0;
        const __half* bp = Bt + (size_t)(colBase + ldRow) * K + k0;
        const uint32_t rsw = (uint32_t)((ldRow & 7) << 4);
        const uint32_t rowoff = (uint32_t)(ldRow << 7);
        #pragma unroll
        for (int j = 0; j < 4; j++) {
            int c = ldCb + j;
            uint32_t off = (rowoff + (uint32_t)(c << 4)) ^ rsw;
            cp_async16(SA[buf] + off, ap + c * 8, av);
            cp_async16(SB[buf] + off, bp + c * 8, true);
        }
    };

    load_tile(0, 0);
    cp_async_commit();

    int buf = 0;
    for (int kt = 0; kt < nkt; kt++) {
        if (kt + 1 < nkt) {
            load_tile(kt + 1, buf ^ 1);
            cp_async_commit();
            cp_async_wait1();
        } else {
            cp_async_wait0();
        }
        __syncthreads();

        const uint32_t sa = SA[buf], sb = SB[buf];
        #pragma unroll
        for (int kk = 0; kk < 4; kk++) {
            uint32_t af[4][4];
            #pragma unroll
            for (int mt = 0; mt < 4; mt++) {
                int r = warpRow * 64 + mt * 16 + aR;
                uint32_t byte = ((uint32_t)(r << 7) + (uint32_t)(kk << 5) + aK)
                                ^ (uint32_t)((r & 7) << 4);
                ldsm4(af[mt][0], af[mt][1], af[mt][2], af[mt][3], sa + byte);
            }
            uint32_t bf[2][4];
            #pragma unroll
            for (int ng = 0; ng < 2; ng++) {
                int r = warpCol * 32 + ng * 16 + bR;
                uint32_t byte = ((uint32_t)(r << 7) + (uint32_t)(kk << 5) + bK)
                                ^ (uint32_t)((r & 7) << 4);
                ldsm4(bf[ng][0], bf[ng][1], bf[ng][2], bf[ng][3], sb + byte);
            }
            #pragma unroll
            for (int mt = 0; mt < 4; mt++) {
                mma_f16(acc[mt][0], af[mt], &bf[0][0]);
                mma_f16(acc[mt][1], af[mt], &bf[0][2]);
                mma_f16(acc[mt][2], af[mt], &bf[1][0]);
                mma_f16(acc[mt][3], af[mt], &bf[1][2]);
            }
        }
        __syncthreads();
        buf ^= 1;
    }

    // ---- epilogue: +bias ----
    #pragma unroll
    for (int nt = 0; nt < 4; nt++) {
        int gn = colBase + warpCol * 32 + nt * 8 + 2 * tg;
        float bx = bias[gn], by = bias[gn + 1];
        #pragma unroll
        for (int mt = 0; mt < 4; mt++) {
            int gm0 = rowBase + warpRow * 64 + mt * 16 + groupID;
            if (gm0 < M) {
                if (HOUT) {
                    __half2 hv = __floats2half2_rn(acc[mt][nt][0] + bx, acc[mt][nt][1] + by);
                    *(__half2*)&((__half*)Cv)[(size_t)gm0 * N + gn] = hv;
                } else {
                    float2 v = make_float2(acc[mt][nt][0] + bx, acc[mt][nt][1] + by);
                    *(float2*)&((float*)Cv)[(size_t)gm0 * N + gn] = v;
                }
            }
            if (gm0 + 8 < M) {
                if (HOUT) {
                    __half2 hv = __floats2half2_rn(acc[mt][nt][2] + bx, acc[mt][nt][3] + by);
                    *(__half2*)&((__half*)Cv)[(size_t)(gm0 + 8) * N + gn] = hv;
                } else {
                    float2 v = make_float2(acc[mt][nt][2] + bx, acc[mt][nt][3] + by);
                    *(float2*)&((float*)Cv)[(size_t)(gm0 + 8) * N + gn] = v;
                }
            }
        }
    }
}

// ---------------- fp16 tensor-core flash attention ----------------
// CTA: BQ=64, BS=64, 128 threads (4 warps, 16 q-rows each). Q frags preloaded.
// K as mma B via ldmatrix; V via ldmatrix.trans; fp32 online softmax; half out.
#define ATILE 16384                     /* 64 rows x 256B */
#define ATTN_SMEM (5 * ATILE)           /* Q + 2x(K,V) = 80KB */

__global__ __launch_bounds__(128) void fattn_kernel()
{
    extern __shared__ char smemc[];
    const uint32_t s0 = smem_u32(smemc);
    const uint32_t SQ = s0;
    const uint32_t SKb[2] = { s0 + ATILE,     s0 + 3 * ATILE };
    const uint32_t SVb[2] = { s0 + 2 * ATILE, s0 + 4 * ATILE };

    const int tid = threadIdx.x, lane = tid & 31, warp = tid >> 5;
    const int g = lane >> 2, tg = lane & 3;
    const int b = blockIdx.z, h = blockIdx.y, qt = blockIdx.x;
    const int q0 = qt * 64;
    const float SCALE = 0.08838834764831845f;

    // ---- Q tile -> smem ----
    {
        int r = tid >> 1;
        int gq = q0 + r;
        bool ok = gq < LQ;
        const __half* src = h_q + ((size_t)b * LQ + (ok ? gq : 0)) * DM + h * DH;
        uint32_t rsw = (uint32_t)((r & 7) << 4);
        #pragma unroll
        for (int j = 0; j < 8; j++) {
            int c = (tid & 1) * 8 + j;
            uint32_t off = ((uint32_t)(r * 256 + c * 16)) ^ rsw;
            cp_async16(SQ + off, src + c * 8, ok);
        }
    }
    cp_async_commit();

    auto loadKV = [&](int it, int bufi) {
        int r = tid >> 1;
        int gs = it * 64 + r;
        bool ok = gs < SK;
        const __half* ks = h_k + (size_t)(ok ? gs : 0) * DM + h * DH;
        const __half* vs = h_v + (size_t)(ok ? gs : 0) * DM + h * DH;
        uint32_t rsw = (uint32_t)((r & 7) << 4);
        #pragma unroll
        for (int j = 0; j < 8; j++) {
            int c = (tid & 1) * 8 + j;
            uint32_t off = ((uint32_t)(r * 256 + c * 16)) ^ rsw;
            cp_async16(SKb[bufi] + off, ks + c * 8, ok);
            cp_async16(SVb[bufi] + off, vs + c * 8, ok);
        }
    };
    loadKV(0, 0);
    cp_async_commit();
    cp_async_wait1();           // Q group done
    __syncthreads();

    // ---- preload Q fragments (8 k-steps x 4 regs) ----
    uint32_t qf[8][4];
    {
        int aR = lane & 15;
        uint32_t aK = (uint32_t)((lane >> 4) & 1) * 16;
        int r = warp * 16 + aR;
        uint32_t rsw = (uint32_t)((r & 7) << 4);
        #pragma unroll
        for (int kk = 0; kk < 8; kk++) {
            uint32_t byte = ((uint32_t)(r * 256 + kk * 32) + aK) ^ rsw;
            ldsm4(qf[kk][0], qf[kk][1], qf[kk][2], qf[kk][3], SQ + byte);
        }
    }

    float acc_o[16][4];
    #pragma unroll
    for (int nt = 0; nt < 16; nt++)
        #pragma unroll
        for (int r = 0; r < 4; r++) acc_o[nt][r] = 0.f;
    float m0 = -CUDART_INF_F, m1 = -CUDART_INF_F, l0 = 0.f, l1 = 0.f;

    const int NST = (SK + 63) / 64;     // 16
    int buf = 0;
    for (int it = 0; it < NST; it++) {
        if (it + 1 < NST) { loadKV(it + 1, buf ^ 1); cp_async_commit(); cp_async_wait1(); }
        else              { cp_async_wait0(); }
        __syncthreads();

        // ---- scores: S[16x64] = Q_w @ K^T ----
        float s[8][4];
        #pragma unroll
        for (int nt = 0; nt < 8; nt++)
            #pragma unroll
            for (int r = 0; r < 4; r++) s[nt][r] = 0.f;
        {
            int bR = (lane & 7) + ((lane >> 4) << 3);
            uint32_t bK = (uint32_t)((lane >> 3) & 1) * 16;
            #pragma unroll
            for (int kk = 0; kk < 8; kk++) {
                uint32_t bfr[4][4];
                #pragma unroll
                for (int ng = 0; ng < 4; ng++) {
                    int r = ng * 16 + bR;
                    uint32_t byte = ((uint32_t)(r * 256 + kk * 32) + bK)
                                    ^ (uint32_t)((r & 7) << 4);
                    ldsm4(bfr[ng][0], bfr[ng][1], bfr[ng][2], bfr[ng][3], SKb[buf] + byte);
                }
                #pragma unroll
                for (int ng = 0; ng < 4; ng++) {
                    mma_f16(s[2 * ng],     qf[kk], &bfr[ng][0]);
                    mma_f16(s[2 * ng + 1], qf[kk], &bfr[ng][2]);
                }
            }
        }

        // ---- scale + mask ----
        int sbase = it * 64;
        #pragma unroll
        for (int nt = 0; nt < 8; nt++) {
            int c0 = sbase + nt * 8 + 2 * tg;
            bool v0 = c0 < SK, v1 = (c0 + 1) < SK;
            s[nt][0] = v0 ? s[nt][0] * SCALE : -CUDART_INF_F;
            s[nt][1] = v1 ? s[nt][1] * SCALE : -CUDART_INF_F;
            s[nt][2] = v0 ? s[nt][2] * SCALE : -CUDART_INF_F;
            s[nt][3] = v1 ? s[nt][3] * SCALE : -CUDART_INF_F;
        }

        // ---- online softmax ----
        float rm0 = -CUDART_INF_F, rm1 = -CUDART_INF_F;
        #pragma unroll
        for (int nt = 0; nt < 8; nt++) {
            rm0 = fmaxf(rm0, fmaxf(s[nt][0], s[nt][1]));
            rm1 = fmaxf(rm1, fmaxf(s[nt][2], s[nt][3]));
        }
        rm0 = fmaxf(rm0, __shfl_xor_sync(0xffffffff, rm0, 1));
        rm0 = fmaxf(rm0, __shfl_xor_sync(0xffffffff, rm0, 2));
        rm1 = fmaxf(rm1, __shfl_xor_sync(0xffffffff, rm1, 1));
        rm1 = fmaxf(rm1, __shfl_xor_sync(0xffffffff, rm1, 2));
        float mn0 = fmaxf(m0, rm0), mn1 = fmaxf(m1, rm1);
        float a0 = __expf(m0 - mn0), a1 = __expf(m1 - mn1);

        float ps0 = 0.f, ps1 = 0.f;
        #pragma unroll
        for (int nt = 0; nt < 8; nt++) {
            s[nt][0] = __expf(s[nt][0] - mn0);
            s[nt][1] = __expf(s[nt][1] - mn0);
            s[nt][2] = __expf(s[nt][2] - mn1);
            s[nt][3] = __expf(s[nt][3] - mn1);
            ps0 += s[nt][0] + s[nt][1];
            ps1 += s[nt][2] + s[nt][3];
        }
        ps0 += __shfl_xor_sync(0xffffffff, ps0, 1);
        ps0 += __shfl_xor_sync(0xffffffff, ps0, 2);
        ps1 += __shfl_xor_sync(0xffffffff, ps1, 1);
        ps1 += __shfl_xor_sync(0xffffffff, ps1, 2);
        l0 = l0 * a0 + ps0;
        l1 = l1 * a1 + ps1;
        m0 = mn0; m1 = mn1;

        #pragma unroll
        for (int nt = 0; nt < 16; nt++) {
            acc_o[nt][0] *= a0; acc_o[nt][1] *= a0;
            acc_o[nt][2] *= a1; acc_o[nt][3] *= a1;
        }

        // ---- pack P into A-fragments (C-frag m16n16 == A-frag m16k16) ----
        uint32_t pf[4][4];
        #pragma unroll
        for (int kt = 0; kt < 4; kt++) {
            pf[kt][0] = h2bits(s[2 * kt][0],     s[2 * kt][1]);
            pf[kt][1] = h2bits(s[2 * kt][2],     s[2 * kt][3]);
            pf[kt][2] = h2bits(s[2 * kt + 1][0], s[2 * kt + 1][1]);
            pf[kt][3] = h2bits(s[2 * kt + 1][2], s[2 * kt + 1][3]);
        }

        // ---- O += P @ V  (V b-frags via ldmatrix.trans) ----
        {
            int vR = lane & 15;
            uint32_t vC = (uint32_t)((lane >> 4) & 1) * 16;
            #pragma unroll
            for (int kt = 0; kt < 4; kt++) {
                int r = kt * 16 + vR;
                uint32_t rsw = (uint32_t)((r & 7) << 4);
                uint32_t rowb = (uint32_t)(r * 256);
                #pragma unroll
                for (int nn = 0; nn < 8; nn++) {
                    uint32_t byte = (rowb + (uint32_t)(nn * 32) + vC) ^ rsw;
                    uint32_t v0, v1, v2, v3;
                    ldsm4t(v0, v1, v2, v3, SVb[buf] + byte);
                    uint32_t bb0[2] = { v0, v1 }, bb1[2] = { v2, v3 };
                    mma_f16(acc_o[2 * nn],     pf[kt], bb0);
                    mma_f16(acc_o[2 * nn + 1], pf[kt], bb1);
                }
            }
        }
        __syncthreads();
        buf ^= 1;
    }

    // ---- epilogue: normalize, write half ----
    float inv0 = 1.f / l0, inv1 = 1.f / l1;
    int gq0 = q0 + warp * 16 + g, gq1 = gq0 + 8;
    #pragma unroll
    for (int nt = 0; nt < 16; nt++) {
        int col = h * DH + nt * 8 + 2 * tg;
        if (gq0 < LQ) {
            __half2 hv = __floats2half2_rn(acc_o[nt][0] * inv0, acc_o[nt][1] * inv0);
            *(__half2*)&h_at[((size_t)b * LQ + gq0) * DM + col] = hv;
        }
        if (gq1 < LQ) {
            __half2 hv = __floats2half2_rn(acc_o[nt][2] * inv1, acc_o[nt][3] * inv1);
            *(__half2*)&h_at[((size_t)b * LQ + gq1) * DM + col] = hv;
        }
    }
}

// ---------------- launcher ----------------
extern "C" void kernel_launch(void* const* d_in, const int* in_sizes, int n_in,
                              void* d_out, int out_size)
{
    const float* tgt = (const float*)d_in[0];
    const float* src = (const float*)d_in[1];
    const float* val = (const float*)d_in[2];
    const float* Wq  = (const float*)d_in[3];
    const float* bq  = (const float*)d_in[4];
    const float* Wk  = (const float*)d_in[5];
    const float* bk  = (const float*)d_in[6];
    const float* Wv  = (const float*)d_in[7];
    const float* bv  = (const float*)d_in[8];
    const float* Wo  = (const float*)d_in[9];
    const float* bo  = (const float*)d_in[10];
    const float* cls = (const float*)d_in[11];

    __half *p_tgt, *p_src, *p_val, *p_q, *p_k, *p_v, *p_at, *p_wqt, *p_wkt, *p_wvt, *p_wot;
    cudaGetSymbolAddress((void**)&p_tgt, h_tgt);
    cudaGetSymbolAddress((void**)&p_src, h_src);
    cudaGetSymbolAddress((void**)&p_val, h_val);
    cudaGetSymbolAddress((void**)&p_q,   h_q);
    cudaGetSymbolAddress((void**)&p_k,   h_k);
    cudaGetSymbolAddress((void**)&p_v,   h_v);
    cudaGetSymbolAddress((void**)&p_at,  h_at);
    cudaGetSymbolAddress((void**)&p_wqt, h_wqt);
    cudaGetSymbolAddress((void**)&p_wkt, h_wkt);
    cudaGetSymbolAddress((void**)&p_wvt, h_wvt);
    cudaGetSymbolAddress((void**)&p_wot, h_wot);

    cudaFuncSetAttribute(hgemm_kernel<true>,  cudaFuncAttributeMaxDynamicSharedMemorySize, HGEMM_SMEM);
    cudaFuncSetAttribute(hgemm_kernel<false>, cudaFuncAttributeMaxDynamicSharedMemorySize, HGEMM_SMEM);
    cudaFuncSetAttribute(fattn_kernel,        cudaFuncAttributeMaxDynamicSharedMemorySize, ATTN_SMEM);

    dim3 tb(32, 8);
    transpose_h_kernel<<<dim3(DM / 32,   DM / 32),   tb>>>(Wq, p_wqt, DM,   DM);
    transpose_h_kernel<<<dim3(DM / 32,   DLLM / 32), tb>>>(Wk, p_wkt, DLLM, DM);
    transpose_h_kernel<<<dim3(DM / 32,   DLLM / 32), tb>>>(Wv, p_wvt, DLLM, DM);
    transpose_h_kernel<<<dim3(DLLM / 32, DM / 32),   tb>>>(Wo, p_wot, DM,   DLLM);

    {
        size_t total = (size_t)MQ * (DM / 4);
        build_tgt_h_kernel<<<(int)((total + 255) / 256), 256>>>(tgt, cls, p_tgt);
        size_t n4 = (size_t)SK * DLLM / 4;
        f2h_kernel<<<(int)((n4 + 255) / 256), 256>>>(src, p_src, n4);
        f2h_kernel<<<(int)((n4 + 255) / 256), 256>>>(val, p_val, n4);
    }

    // Q = tgt @ Wq + bq            [16416,1024]  (half out)
    hgemm_kernel<true><<<dim3(DM / 128, (MQ + 127) / 128), 256, HGEMM_SMEM>>>(p_tgt, p_wqt, bq, p_q, MQ, DM, DM);
    // K = src @ Wk + bk            [1000,1024]   (half out)
    hgemm_kernel<true><<<dim3(DM / 128, (SK + 127) / 128), 256, HGEMM_SMEM>>>(p_src, p_wkt, bk, p_k, SK, DM, DLLM);
    // V = val @ Wv + bv                          (half out)
    hgemm_kernel<true><<<dim3(DM / 128, (SK + 127) / 128), 256, HGEMM_SMEM>>>(p_val, p_wvt, bv, p_v, SK, DM, DLLM);
    // attention (half in, half out)
    fattn_kernel<<<dim3((LQ + 63) / 64, NH, B_), 128, ATTN_SMEM>>>();
    // out = attn @ Wo + bo         [16416,4096]  (float out)
    hgemm_kernel<false><<<dim3(DLLM / 128, (MQ + 127) / 128), 256, HGEMM_SMEM>>>(p_at, p_wot, bo, d_out, MQ, DLLM, DM);
}